// round 1
// baseline (speedup 1.0000x reference)
#include <cuda_runtime.h>
#include <cuda_bf16.h>

// ---------------------------------------------------------------------------
// Fused LSTM(2)->bridge->GRU(2, autoregressive)->MLP predictor.
// B=2048, H=128, S=64, pred_len read from device. Each block owns 8 rows.
// Weights are pre-fused/transposed into gate-major float4-vectorized layout
// by a prep kernel into __device__ scratch (no allocations).
// ---------------------------------------------------------------------------

#define NROWS 8
#define NTHREADS 512
#define NBLOCKS 256   // 2048 / 8
#define SEQ 64
#define H 128

// ----- scratch layout (floats) -----
#define N_W0   (33*512*4)   // LSTM l0: [x(4);h0(128)] -> 512 gates, K=132 (K4=33)
#define N_W1   (64*512*4)   // LSTM l1: [h0;h1] -> 512 gates, K=256
#define N_GRZ  (64*256*4)   // GRU r,z: [x;h] -> 256 gates, K=256
#define N_WN   (32*128*4)   // GRU n (in or hn): 128 gates, K=128
#define N_BR   (32*128*4)   // bridge: 128 out, K=128
#define N_FC1  (32*64*4)    // fc1: 64 out, K=128

#define OFF_W0    0
#define OFF_W1    67584
#define OFF_GRZ0  198656
#define OFF_GRZ1  264192
#define OFF_WIN0  329728
#define OFF_WHN0  346112
#define OFF_WIN1  362496
#define OFF_WHN1  378880
#define OFF_BR    395264
#define OFF_FC1   411648
#define OFF_B0    419840
#define OFF_B1    420352
#define OFF_BRZ0  420864
#define OFF_BRZ1  421120
#define OFF_BIN0  421376
#define OFF_BHN0  421504
#define OFF_BIN1  421632
#define OFF_BHN1  421760
#define OFF_BB    421888
#define OFF_FC1B  422016
#define SCRATCH_TOTAL 422080

__device__ __align__(16) float g_scratch[SCRATCH_TOTAL];

// ---------------------------------------------------------------------------
// Prep kernel: build fused/transposed/vectorized weights.
// Vectorized layout per matrix segment: float element index
//   i = (k4*GW + g)*4 + kk, where k = 4*k4 + kk  (GW = number of gate rows)
// ---------------------------------------------------------------------------
__global__ void prep_kernel(
    const float* __restrict__ wih0, const float* __restrict__ whh0,
    const float* __restrict__ bih0, const float* __restrict__ bhh0,
    const float* __restrict__ wih1, const float* __restrict__ whh1,
    const float* __restrict__ bih1, const float* __restrict__ bhh1,
    const float* __restrict__ gwih0, const float* __restrict__ gwhh0,
    const float* __restrict__ gbih0, const float* __restrict__ gbhh0,
    const float* __restrict__ gwih1, const float* __restrict__ gwhh1,
    const float* __restrict__ gbih1, const float* __restrict__ gbhh1,
    const float* __restrict__ brw,  const float* __restrict__ brb,
    const float* __restrict__ fc1w, const float* __restrict__ fc1b)
{
    int idx = blockIdx.x * blockDim.x + threadIdx.x;
    if (idx >= SCRATCH_TOTAL) return;
    float v = 0.0f;

    if (idx < OFF_W1) {                      // LSTM l0: K = [x(4); h0(128)]
        int i = idx - OFF_W0;
        int kk = i & 3; int j = i >> 2; int g = j & 511; int k4 = j >> 9;
        int k = 4*k4 + kk;
        v = (k < 4) ? wih0[g*4 + k] : whh0[g*128 + (k - 4)];
    } else if (idx < OFF_GRZ0) {             // LSTM l1: K = [h0;h1]
        int i = idx - OFF_W1;
        int kk = i & 3; int j = i >> 2; int g = j & 511; int k4 = j >> 9;
        int k = 4*k4 + kk;
        v = (k < 128) ? wih1[g*128 + k] : whh1[g*128 + (k - 128)];
    } else if (idx < OFF_GRZ1) {             // GRU l0 r,z: K = [x;h]
        int i = idx - OFF_GRZ0;
        int kk = i & 3; int j = i >> 2; int g = j & 255; int k4 = j >> 8;
        int k = 4*k4 + kk;
        v = (k < 128) ? gwih0[g*128 + k] : gwhh0[g*128 + (k - 128)];
    } else if (idx < OFF_WIN0) {             // GRU l1 r,z
        int i = idx - OFF_GRZ1;
        int kk = i & 3; int j = i >> 2; int g = j & 255; int k4 = j >> 8;
        int k = 4*k4 + kk;
        v = (k < 128) ? gwih1[g*128 + k] : gwhh1[g*128 + (k - 128)];
    } else if (idx < OFF_WHN0) {             // GRU l0 n (input part)
        int i = idx - OFF_WIN0;
        int kk = i & 3; int j = i >> 2; int g = j & 127; int k4 = j >> 7;
        v = gwih0[(256 + g)*128 + 4*k4 + kk];
    } else if (idx < OFF_WIN1) {             // GRU l0 n (hidden part)
        int i = idx - OFF_WHN0;
        int kk = i & 3; int j = i >> 2; int g = j & 127; int k4 = j >> 7;
        v = gwhh0[(256 + g)*128 + 4*k4 + kk];
    } else if (idx < OFF_WHN1) {             // GRU l1 n (input part)
        int i = idx - OFF_WIN1;
        int kk = i & 3; int j = i >> 2; int g = j & 127; int k4 = j >> 7;
        v = gwih1[(256 + g)*128 + 4*k4 + kk];
    } else if (idx < OFF_BR) {               // GRU l1 n (hidden part)
        int i = idx - OFF_WHN1;
        int kk = i & 3; int j = i >> 2; int g = j & 127; int k4 = j >> 7;
        v = gwhh1[(256 + g)*128 + 4*k4 + kk];
    } else if (idx < OFF_FC1) {              // bridge
        int i = idx - OFF_BR;
        int kk = i & 3; int j = i >> 2; int g = j & 127; int k4 = j >> 7;
        v = brw[g*128 + 4*k4 + kk];
    } else if (idx < OFF_B0) {               // fc1
        int i = idx - OFF_FC1;
        int kk = i & 3; int j = i >> 2; int g = j & 63; int k4 = j >> 6;
        v = fc1w[g*128 + 4*k4 + kk];
    } else if (idx < OFF_B1)   { int i = idx - OFF_B0;   v = bih0[i] + bhh0[i]; }
    else if (idx < OFF_BRZ0)   { int i = idx - OFF_B1;   v = bih1[i] + bhh1[i]; }
    else if (idx < OFF_BRZ1)   { int i = idx - OFF_BRZ0; v = gbih0[i] + gbhh0[i]; }
    else if (idx < OFF_BIN0)   { int i = idx - OFF_BRZ1; v = gbih1[i] + gbhh1[i]; }
    else if (idx < OFF_BHN0)   { int i = idx - OFF_BIN0; v = gbih0[256 + i]; }
    else if (idx < OFF_BIN1)   { int i = idx - OFF_BHN0; v = gbhh0[256 + i]; }
    else if (idx < OFF_BHN1)   { int i = idx - OFF_BIN1; v = gbih1[256 + i]; }
    else if (idx < OFF_BB)     { int i = idx - OFF_BHN1; v = gbhh1[256 + i]; }
    else if (idx < OFF_FC1B)   { int i = idx - OFF_BB;   v = brb[i]; }
    else                       { int i = idx - OFF_FC1B; v = fc1b[i]; }

    g_scratch[idx] = v;
}

// ---------------------------------------------------------------------------
// Activations (exp-based; clamped so fast division is safe under any flags)
// ---------------------------------------------------------------------------
__device__ __forceinline__ float sigf(float x) {
    x = fminf(fmaxf(x, -30.f), 30.f);
    return 1.f / (1.f + __expf(-x));
}
__device__ __forceinline__ float tanhfast(float x) {
    x = fminf(fmaxf(x, -15.f), 15.f);
    float e = __expf(2.f * x);
    return 1.f - 2.f / (e + 1.f);
}

// ---------------------------------------------------------------------------
// 8-row gate dot: weights gate-major float4 (LDG.128 from L2, reused across
// 8 rows); state rows read as broadcast LDS.128 (conflict-free).
// ---------------------------------------------------------------------------
template<int GW, int K4>
__device__ __forceinline__ void dot8(const float* __restrict__ wbase, int g,
                                     const float (*st)[384], int koff,
                                     float acc[NROWS])
{
    const float4* w4 = reinterpret_cast<const float4*>(wbase);
    #pragma unroll 4
    for (int k4 = 0; k4 < K4; ++k4) {
        float4 w = __ldg(&w4[k4 * GW + g]);
        #pragma unroll
        for (int r = 0; r < NROWS; ++r) {
            float4 s = *reinterpret_cast<const float4*>(&st[r][koff + 4*k4]);
            acc[r] = fmaf(w.x, s.x, acc[r]);
            acc[r] = fmaf(w.y, s.y, acc[r]);
            acc[r] = fmaf(w.z, s.z, acc[r]);
            acc[r] = fmaf(w.w, s.w, acc[r]);
        }
    }
}

template<int GW, int K4>
__device__ __forceinline__ float dot1(const float* __restrict__ wbase, int g,
                                      const float* __restrict__ srow, float acc)
{
    const float4* w4 = reinterpret_cast<const float4*>(wbase);
    const float4* s4 = reinterpret_cast<const float4*>(srow);
    #pragma unroll 4
    for (int k4 = 0; k4 < K4; ++k4) {
        float4 w = __ldg(&w4[k4 * GW + g]);
        float4 s = s4[k4];
        acc = fmaf(w.x, s.x, acc);
        acc = fmaf(w.y, s.y, acc);
        acc = fmaf(w.z, s.z, acc);
        acc = fmaf(w.w, s.w, acc);
    }
    return acc;
}

// ---------------------------------------------------------------------------
// Main fused kernel
// ---------------------------------------------------------------------------
__global__ void __launch_bounds__(NTHREADS, 2)
fused_kernel(const float* __restrict__ x, const int* __restrict__ plen_p,
             const float* __restrict__ fc2w, const float* __restrict__ fc2b,
             float* __restrict__ out)
{
    // state row layout (floats):
    //  LSTM phase: [x(4) | h0(128) | h1(128) | pad]
    //  GRU  phase: [inp(128) | hd0(128) | hd1(128)]
    __shared__ float st[NROWS][384];
    __shared__ float c0s[NROWS][H];
    __shared__ float c1s[NROWS][H];
    __shared__ float gb[NROWS][512];

    const int tid = threadIdx.x;
    const int rbase = blockIdx.x * NROWS;
    const float* S = g_scratch;

    // zero all state
    for (int i = tid; i < NROWS * 384; i += NTHREADS) (&st[0][0])[i] = 0.f;
    for (int i = tid; i < NROWS * H; i += NTHREADS) { (&c0s[0][0])[i] = 0.f; (&c1s[0][0])[i] = 0.f; }
    __syncthreads();

    const float b0 = S[OFF_B0 + tid];
    const float b1 = S[OFF_B1 + tid];

    // ---------------- LSTM encoder: 64 steps, 2 layers ----------------
    for (int t = 0; t < SEQ; ++t) {
        if (tid < 32) {
            int r = tid >> 2, k = tid & 3;
            st[r][k] = x[((rbase + r) * SEQ + t) * 4 + k];
        }
        __syncthreads();

        // layer 0 gates: [x;h0] (K=132) -> 512 gates
        {
            float acc[NROWS];
            #pragma unroll
            for (int r = 0; r < NROWS; ++r) acc[r] = b0;
            dot8<512, 33>(S + OFF_W0, tid, st, 0, acc);
            #pragma unroll
            for (int r = 0; r < NROWS; ++r) gb[r][tid] = acc[r];
        }
        __syncthreads();
        // layer 0 update (h0 at offset 4)
        #pragma unroll
        for (int p = 0; p < 2; ++p) {
            int idx = tid + p * NTHREADS;
            int r = idx >> 7, d = idx & 127;
            float gi = sigf(gb[r][d]);
            float gf = sigf(gb[r][128 + d]);
            float gg = tanhfast(gb[r][256 + d]);
            float go = sigf(gb[r][384 + d]);
            float cn = gf * c0s[r][d] + gi * gg;
            c0s[r][d] = cn;
            st[r][4 + d] = go * tanhfast(cn);
        }
        __syncthreads();

        // layer 1 gates: [h0;h1] (K=256, offset 4)
        {
            float acc[NROWS];
            #pragma unroll
            for (int r = 0; r < NROWS; ++r) acc[r] = b1;
            dot8<512, 64>(S + OFF_W1, tid, st, 4, acc);
            #pragma unroll
            for (int r = 0; r < NROWS; ++r) gb[r][tid] = acc[r];
        }
        __syncthreads();
        // layer 1 update (h1 at offset 132)
        #pragma unroll
        for (int p = 0; p < 2; ++p) {
            int idx = tid + p * NTHREADS;
            int r = idx >> 7, d = idx & 127;
            float gi = sigf(gb[r][d]);
            float gf = sigf(gb[r][128 + d]);
            float gg = tanhfast(gb[r][256 + d]);
            float go = sigf(gb[r][384 + d]);
            float cn = gf * c1s[r][d] + gi * gg;
            c1s[r][d] = cn;
            st[r][132 + d] = go * tanhfast(cn);
        }
        __syncthreads();
    }

    // ---------------- bridge: hg_l = tanh(h_l @ Wb^T + bb) ----------------
    // 2048 dots (2 layers x 8 rows x 128 dims) -> 4 per thread -> gb
    #pragma unroll
    for (int p = 0; p < 4; ++p) {
        int idx = tid + p * NTHREADS;          // [0, 2048)
        int l = idx >> 10;
        int rem = idx & 1023;
        int r = rem >> 7, d = rem & 127;
        float acc = S[OFF_BB + d];
        acc = dot1<128, 32>(S + OFF_BR, d, &st[r][4 + 128 * l], acc);
        gb[r][l * 128 + d] = tanhfast(acc);
    }
    __syncthreads();
    // restage state for GRU: inp = h1(final), hd0 = hg0, hd1 = hg1
    {
        float inpv[2], g0v[2], g1v[2];
        #pragma unroll
        for (int p = 0; p < 2; ++p) {
            int idx = tid + p * NTHREADS;
            int r = idx >> 7, d = idx & 127;
            inpv[p] = st[r][132 + d];
            g0v[p] = gb[r][d];
            g1v[p] = gb[r][128 + d];
        }
        __syncthreads();
        #pragma unroll
        for (int p = 0; p < 2; ++p) {
            int idx = tid + p * NTHREADS;
            int r = idx >> 7, d = idx & 127;
            st[r][d] = inpv[p];
            st[r][128 + d] = g0v[p];
            st[r][256 + d] = g1v[p];
        }
    }
    __syncthreads();

    // ---------------- GRU decoder + head ----------------
    const int plen = plen_p[0];
    for (int td = 0; td < plen; ++td) {
        #pragma unroll
        for (int l = 0; l < 2; ++l) {
            const int xoff = l ? 128 : 0;
            const float* grz = S + (l ? OFF_GRZ1 : OFF_GRZ0);
            const float* win = S + (l ? OFF_WIN1 : OFF_WIN0);
            const float* whn = S + (l ? OFF_WHN1 : OFF_WHN0);
            const int obrz = l ? OFF_BRZ1 : OFF_BRZ0;
            const int obin = l ? OFF_BIN1 : OFF_BIN0;
            const int obhn = l ? OFF_BHN1 : OFF_BHN0;

            float acc[NROWS];
            if (tid < 256) {
                // combined r,z gates over [x;h] (K=256)
                float b = S[obrz + tid];
                #pragma unroll
                for (int r = 0; r < NROWS; ++r) acc[r] = b;
                dot8<256, 64>(grz, tid, st, xoff, acc);
            } else if (tid < 384) {
                // n gate, input part (K=128 over x)
                int g = tid - 256;
                float b = S[obin + g];
                #pragma unroll
                for (int r = 0; r < NROWS; ++r) acc[r] = b;
                dot8<128, 32>(win, g, st, xoff, acc);
            } else {
                // n gate, hidden part (K=128 over h)
                int g = tid - 384;
                float b = S[obhn + g];
                #pragma unroll
                for (int r = 0; r < NROWS; ++r) acc[r] = b;
                dot8<128, 32>(whn, g, st, xoff + 128, acc);
            }
            #pragma unroll
            for (int r = 0; r < NROWS; ++r) gb[r][tid] = acc[r];
            __syncthreads();

            // update h_l (at offset xoff+128); for l==1 also write next inp
            #pragma unroll
            for (int p = 0; p < 2; ++p) {
                int idx = tid + p * NTHREADS;
                int r = idx >> 7, d = idx & 127;
                float rv = sigf(gb[r][d]);
                float zv = sigf(gb[r][128 + d]);
                float nv = tanhfast(gb[r][256 + d] + rv * gb[r][384 + d]);
                float hold = st[r][xoff + 128 + d];
                float hnew = (1.f - zv) * nv + zv * hold;
                st[r][xoff + 128 + d] = hnew;
                if (l == 1) st[r][d] = hnew;
            }
            __syncthreads();
        }

        // head: fc1 (relu) then fc2
        {
            int r = tid >> 6, j = tid & 63;
            float acc = S[OFF_FC1B + j];
            acc = dot1<64, 32>(S + OFF_FC1, j, &st[r][256], acc);
            gb[r][j] = fmaxf(acc, 0.f);
        }
        __syncthreads();
        if (tid < 16) {
            int r = tid >> 1, o = tid & 1;
            float a = fc2b[o];
            #pragma unroll 8
            for (int k = 0; k < 64; ++k) a = fmaf(fc2w[o * 64 + k], gb[r][k], a);
            out[((rbase + r) * plen + td) * 2 + o] = a;
        }
        __syncthreads();
    }
}

// ---------------------------------------------------------------------------
// launch
// ---------------------------------------------------------------------------
extern "C" void kernel_launch(void* const* d_in, const int* in_sizes, int n_in,
                              void* d_out, int out_size)
{
    const float* x        = (const float*)d_in[0];
    const int*   pred_len = (const int*)  d_in[1];
    const float* wih0  = (const float*)d_in[2];
    const float* whh0  = (const float*)d_in[3];
    const float* bih0  = (const float*)d_in[4];
    const float* bhh0  = (const float*)d_in[5];
    const float* wih1  = (const float*)d_in[6];
    const float* whh1  = (const float*)d_in[7];
    const float* bih1  = (const float*)d_in[8];
    const float* bhh1  = (const float*)d_in[9];
    const float* gwih0 = (const float*)d_in[10];
    const float* gwhh0 = (const float*)d_in[11];
    const float* gbih0 = (const float*)d_in[12];
    const float* gbhh0 = (const float*)d_in[13];
    const float* gwih1 = (const float*)d_in[14];
    const float* gwhh1 = (const float*)d_in[15];
    const float* gbih1 = (const float*)d_in[16];
    const float* gbhh1 = (const float*)d_in[17];
    const float* brw   = (const float*)d_in[18];
    const float* brb   = (const float*)d_in[19];
    const float* fc1w  = (const float*)d_in[20];
    const float* fc1b  = (const float*)d_in[21];
    const float* fc2w  = (const float*)d_in[22];
    const float* fc2b  = (const float*)d_in[23];
    float* out = (float*)d_out;

    int prep_blocks = (SCRATCH_TOTAL + 255) / 256;
    prep_kernel<<<prep_blocks, 256>>>(wih0, whh0, bih0, bhh0,
                                      wih1, whh1, bih1, bhh1,
                                      gwih0, gwhh0, gbih0, gbhh0,
                                      gwih1, gwhh1, gbih1, gbhh1,
                                      brw, brb, fc1w, fc1b);
    fused_kernel<<<NBLOCKS, NTHREADS>>>(x, pred_len, fc2w, fc2b, out);
}

// round 3
// speedup vs baseline: 1.2130x; 1.2130x over previous
#include <cuda_runtime.h>
#include <cuda_bf16.h>

// ---------------------------------------------------------------------------
// Fused LSTM(2)->bridge->GRU(2, autoregressive)->MLP predictor.
// B=2048, H=128, S=64. 128 blocks x 16 rows, 512 threads.
// Register tiling: 4 gates x 4 rows per thread; fma.rn.f32x2 packed over k.
// ---------------------------------------------------------------------------

#define NROWS 16
#define NTHREADS 512
#define NBLOCKS 128   // 2048 / 16
#define SEQ 64
#define H 128

// ----- scratch layout (floats), identical to validated round-1 layout -----
#define OFF_W0    0
#define OFF_W1    67584
#define OFF_GRZ0  198656
#define OFF_GRZ1  264192
#define OFF_WIN0  329728
#define OFF_WHN0  346112
#define OFF_WIN1  362496
#define OFF_WHN1  378880
#define OFF_BR    395264
#define OFF_FC1   411648
#define OFF_B0    419840
#define OFF_B1    420352
#define OFF_BRZ0  420864
#define OFF_BRZ1  421120
#define OFF_BIN0  421376
#define OFF_BHN0  421504
#define OFF_BIN1  421632
#define OFF_BHN1  421760
#define OFF_BB    421888
#define OFF_FC1B  422016
#define SCRATCH_TOTAL 422080

__device__ __align__(16) float g_scratch[SCRATCH_TOTAL];

// dynamic smem layout (floats)
#define SM_ST   0                 // st[16][384]
#define SM_C0   (16*384)          // c0s[16][128]
#define SM_C1   (SM_C0 + 16*128)  // c1s[16][128]
#define SM_GB   (SM_C1 + 16*128)  // gb[16][512]
#define SM_TOTAL (SM_GB + 16*512) // 18432 floats = 73728 bytes
#define SMEM_BYTES (SM_TOTAL * 4)

// ---------------------------------------------------------------------------
// Prep kernel (unchanged from validated version)
// ---------------------------------------------------------------------------
__global__ void prep_kernel(
    const float* __restrict__ wih0, const float* __restrict__ whh0,
    const float* __restrict__ bih0, const float* __restrict__ bhh0,
    const float* __restrict__ wih1, const float* __restrict__ whh1,
    const float* __restrict__ bih1, const float* __restrict__ bhh1,
    const float* __restrict__ gwih0, const float* __restrict__ gwhh0,
    const float* __restrict__ gbih0, const float* __restrict__ gbhh0,
    const float* __restrict__ gwih1, const float* __restrict__ gwhh1,
    const float* __restrict__ gbih1, const float* __restrict__ gbhh1,
    const float* __restrict__ brw,  const float* __restrict__ brb,
    const float* __restrict__ fc1w, const float* __restrict__ fc1b)
{
    int idx = blockIdx.x * blockDim.x + threadIdx.x;
    if (idx >= SCRATCH_TOTAL) return;
    float v = 0.0f;

    if (idx < OFF_W1) {
        int i = idx - OFF_W0;
        int kk = i & 3; int j = i >> 2; int g = j & 511; int k4 = j >> 9;
        int k = 4*k4 + kk;
        v = (k < 4) ? wih0[g*4 + k] : whh0[g*128 + (k - 4)];
    } else if (idx < OFF_GRZ0) {
        int i = idx - OFF_W1;
        int kk = i & 3; int j = i >> 2; int g = j & 511; int k4 = j >> 9;
        int k = 4*k4 + kk;
        v = (k < 128) ? wih1[g*128 + k] : whh1[g*128 + (k - 128)];
    } else if (idx < OFF_GRZ1) {
        int i = idx - OFF_GRZ0;
        int kk = i & 3; int j = i >> 2; int g = j & 255; int k4 = j >> 8;
        int k = 4*k4 + kk;
        v = (k < 128) ? gwih0[g*128 + k] : gwhh0[g*128 + (k - 128)];
    } else if (idx < OFF_WIN0) {
        int i = idx - OFF_GRZ1;
        int kk = i & 3; int j = i >> 2; int g = j & 255; int k4 = j >> 8;
        int k = 4*k4 + kk;
        v = (k < 128) ? gwih1[g*128 + k] : gwhh1[g*128 + (k - 128)];
    } else if (idx < OFF_WHN0) {
        int i = idx - OFF_WIN0;
        int kk = i & 3; int j = i >> 2; int g = j & 127; int k4 = j >> 7;
        v = gwih0[(256 + g)*128 + 4*k4 + kk];
    } else if (idx < OFF_WIN1) {
        int i = idx - OFF_WHN0;
        int kk = i & 3; int j = i >> 2; int g = j & 127; int k4 = j >> 7;
        v = gwhh0[(256 + g)*128 + 4*k4 + kk];
    } else if (idx < OFF_WHN1) {
        int i = idx - OFF_WIN1;
        int kk = i & 3; int j = i >> 2; int g = j & 127; int k4 = j >> 7;
        v = gwih1[(256 + g)*128 + 4*k4 + kk];
    } else if (idx < OFF_BR) {
        int i = idx - OFF_WHN1;
        int kk = i & 3; int j = i >> 2; int g = j & 127; int k4 = j >> 7;
        v = gwhh1[(256 + g)*128 + 4*k4 + kk];
    } else if (idx < OFF_FC1) {
        int i = idx - OFF_BR;
        int kk = i & 3; int j = i >> 2; int g = j & 127; int k4 = j >> 7;
        v = brw[g*128 + 4*k4 + kk];
    } else if (idx < OFF_B0) {
        int i = idx - OFF_FC1;
        int kk = i & 3; int j = i >> 2; int g = j & 63; int k4 = j >> 6;
        v = fc1w[g*128 + 4*k4 + kk];
    } else if (idx < OFF_B1)   { int i = idx - OFF_B0;   v = bih0[i] + bhh0[i]; }
    else if (idx < OFF_BRZ0)   { int i = idx - OFF_B1;   v = bih1[i] + bhh1[i]; }
    else if (idx < OFF_BRZ1)   { int i = idx - OFF_BRZ0; v = gbih0[i] + gbhh0[i]; }
    else if (idx < OFF_BIN0)   { int i = idx - OFF_BRZ1; v = gbih1[i] + gbhh1[i]; }
    else if (idx < OFF_BHN0)   { int i = idx - OFF_BIN0; v = gbih0[256 + i]; }
    else if (idx < OFF_BIN1)   { int i = idx - OFF_BHN0; v = gbhh0[256 + i]; }
    else if (idx < OFF_BHN1)   { int i = idx - OFF_BIN1; v = gbih1[256 + i]; }
    else if (idx < OFF_BB)     { int i = idx - OFF_BHN1; v = gbhh1[256 + i]; }
    else if (idx < OFF_FC1B)   { int i = idx - OFF_BB;   v = brb[i]; }
    else                       { int i = idx - OFF_FC1B; v = fc1b[i]; }

    g_scratch[idx] = v;
}

// ---------------------------------------------------------------------------
// Activations
// ---------------------------------------------------------------------------
__device__ __forceinline__ float sigf(float x) {
    x = fminf(fmaxf(x, -30.f), 30.f);
    return 1.f / (1.f + __expf(-x));
}
__device__ __forceinline__ float tanhfast(float x) {
    x = fminf(fmaxf(x, -15.f), 15.f);
    float e = __expf(2.f * x);
    return 1.f - 2.f / (e + 1.f);
}

// ---------------------------------------------------------------------------
// Packed f32x2 FMA: d = a*b + d (elementwise on 2 packed floats)
// ---------------------------------------------------------------------------
__device__ __forceinline__ void ffma2(unsigned long long& d,
                                      unsigned long long a,
                                      unsigned long long b) {
    asm("fma.rn.f32x2 %0, %1, %2, %0;" : "+l"(d) : "l"(a), "l"(b));
}
__device__ __forceinline__ float red2(unsigned long long a) {
    float lo = __uint_as_float((unsigned)(a & 0xffffffffull));
    float hi = __uint_as_float((unsigned)(a >> 32));
    return lo + hi;
}

// ---------------------------------------------------------------------------
// Tiled gate dot: 4 gates (g0 + i*GW/4) x 4 rows (stp + j*384), K = 4*K4.
// acc[i][j] holds f32x2 {even-k, odd-k} partial sums.
// Weights: float4-vectorized gate-major (index k4*GW + g). State: smem rows.
// ---------------------------------------------------------------------------
template<int GW, int K4>
__device__ __forceinline__ void dotKP(const float* __restrict__ wbase, int g0,
                                      const float* __restrict__ stp,
                                      unsigned long long acc[4][4])
{
    const ulonglong2* wq = reinterpret_cast<const ulonglong2*>(wbase);
    #pragma unroll 4
    for (int k4 = 0; k4 < K4; ++k4) {
        ulonglong2 w[4];
        #pragma unroll
        for (int i = 0; i < 4; ++i)
            w[i] = __ldg(&wq[k4 * GW + g0 + i * (GW / 4)]);
        #pragma unroll
        for (int j = 0; j < 4; ++j) {
            ulonglong2 s = *reinterpret_cast<const ulonglong2*>(stp + j * 384 + 4 * k4);
            #pragma unroll
            for (int i = 0; i < 4; ++i) {
                ffma2(acc[i][j], w[i].x, s.x);
                ffma2(acc[i][j], w[i].y, s.y);
            }
        }
    }
}

// scalar single-row dot (bridge / fc1)
template<int GW, int K4>
__device__ __forceinline__ float dot1(const float* __restrict__ wbase, int g,
                                      const float* __restrict__ srow, float acc)
{
    const float4* w4 = reinterpret_cast<const float4*>(wbase);
    const float4* s4 = reinterpret_cast<const float4*>(srow);
    #pragma unroll 4
    for (int k4 = 0; k4 < K4; ++k4) {
        float4 w = __ldg(&w4[k4 * GW + g]);
        float4 s = s4[k4];
        acc = fmaf(w.x, s.x, acc);
        acc = fmaf(w.y, s.y, acc);
        acc = fmaf(w.z, s.z, acc);
        acc = fmaf(w.w, s.w, acc);
    }
    return acc;
}

// ---------------------------------------------------------------------------
// Main fused kernel
// ---------------------------------------------------------------------------
__global__ void __launch_bounds__(NTHREADS, 1)
fused_kernel(const float* __restrict__ x, const int* __restrict__ plen_p,
             const float* __restrict__ fc2w, const float* __restrict__ fc2b,
             float* __restrict__ out)
{
    extern __shared__ float sm[];
    float (*st)[384]  = (float (*)[384])(sm + SM_ST);
    float (*c0s)[128] = (float (*)[128])(sm + SM_C0);
    float (*c1s)[128] = (float (*)[128])(sm + SM_C1);
    float (*gb)[512]  = (float (*)[512])(sm + SM_GB);
    __shared__ float fc2ws[128];
    __shared__ float fc2bs[2];

    const int tid = threadIdx.x;
    const int rbase = blockIdx.x * NROWS;
    const float* S = g_scratch;

    // zero state, stage fc2
    for (int i = tid; i < SM_TOTAL; i += NTHREADS) sm[i] = 0.f;
    if (tid < 128) fc2ws[tid] = fc2w[tid];
    if (tid < 2) fc2bs[tid] = fc2b[tid];
    __syncthreads();

    // LSTM thread mapping: gq in [0,128), rq4 = row group * 4
    const int gq  = tid & 127;
    const int rq4 = (tid >> 7) << 2;
    float bl0[4], bl1[4];
    #pragma unroll
    for (int i = 0; i < 4; ++i) {
        bl0[i] = S[OFF_B0 + gq + 128 * i];
        bl1[i] = S[OFF_B1 + gq + 128 * i];
    }

    // ---------------- LSTM encoder ----------------
    for (int t = 0; t < SEQ; ++t) {
        if (tid < 64) {
            int r = tid >> 2, k = tid & 3;
            st[r][k] = x[((rbase + r) * SEQ + t) * 4 + k];
        }
        __syncthreads();

        // layer 0: [x;h0], K=132
        {
            unsigned long long acc[4][4];
            #pragma unroll
            for (int i = 0; i < 4; ++i)
                #pragma unroll
                for (int j = 0; j < 4; ++j) acc[i][j] = 0ull;
            dotKP<512, 33>(S + OFF_W0, gq, &st[rq4][0], acc);
            #pragma unroll
            for (int i = 0; i < 4; ++i)
                #pragma unroll
                for (int j = 0; j < 4; ++j)
                    gb[rq4 + j][gq + 128 * i] = bl0[i] + red2(acc[i][j]);
        }
        __syncthreads();
        #pragma unroll
        for (int p = 0; p < 4; ++p) {
            int idx = tid + p * NTHREADS;
            int r = idx >> 7, d = idx & 127;
            float gi = sigf(gb[r][d]);
            float gf = sigf(gb[r][128 + d]);
            float gg = tanhfast(gb[r][256 + d]);
            float go = sigf(gb[r][384 + d]);
            float cn = gf * c0s[r][d] + gi * gg;
            c0s[r][d] = cn;
            st[r][4 + d] = go * tanhfast(cn);
        }
        __syncthreads();

        // layer 1: [h0;h1], K=256 (offset 4)
        {
            unsigned long long acc[4][4];
            #pragma unroll
            for (int i = 0; i < 4; ++i)
                #pragma unroll
                for (int j = 0; j < 4; ++j) acc[i][j] = 0ull;
            dotKP<512, 64>(S + OFF_W1, gq, &st[rq4][4], acc);
            #pragma unroll
            for (int i = 0; i < 4; ++i)
                #pragma unroll
                for (int j = 0; j < 4; ++j)
                    gb[rq4 + j][gq + 128 * i] = bl1[i] + red2(acc[i][j]);
        }
        __syncthreads();
        #pragma unroll
        for (int p = 0; p < 4; ++p) {
            int idx = tid + p * NTHREADS;
            int r = idx >> 7, d = idx & 127;
            float gi = sigf(gb[r][d]);
            float gf = sigf(gb[r][128 + d]);
            float gg = tanhfast(gb[r][256 + d]);
            float go = sigf(gb[r][384 + d]);
            float cn = gf * c1s[r][d] + gi * gg;
            c1s[r][d] = cn;
            st[r][132 + d] = go * tanhfast(cn);
        }
        __syncthreads();
    }

    // ---------------- bridge: hg_l = tanh(h_l @ Wb^T + bb) ----------------
    #pragma unroll
    for (int p = 0; p < 8; ++p) {
        int idx = tid + p * NTHREADS;          // [0, 4096)
        int l = idx >> 11;
        int rem = idx & 2047;
        int r = rem >> 7, d = rem & 127;
        float acc = S[OFF_BB + d];
        acc = dot1<128, 32>(S + OFF_BR, d, &st[r][4 + 128 * l], acc);
        gb[r][l * 128 + d] = tanhfast(acc);
    }
    __syncthreads();
    // restage: inp = h1(final), hd0 = hg0, hd1 = hg1
    {
        float inpv[4], g0v[4], g1v[4];
        #pragma unroll
        for (int p = 0; p < 4; ++p) {
            int idx = tid + p * NTHREADS;
            int r = idx >> 7, d = idx & 127;
            inpv[p] = st[r][132 + d];
            g0v[p] = gb[r][d];
            g1v[p] = gb[r][128 + d];
        }
        __syncthreads();
        #pragma unroll
        for (int p = 0; p < 4; ++p) {
            int idx = tid + p * NTHREADS;
            int r = idx >> 7, d = idx & 127;
            st[r][d] = inpv[p];
            st[r][128 + d] = g0v[p];
            st[r][256 + d] = g1v[p];
        }
    }
    __syncthreads();

    // GRU per-role bias preload
    float gbias[2][4];
    if (tid < 256) {
        int g = tid & 63;
        #pragma unroll
        for (int i = 0; i < 4; ++i) {
            gbias[0][i] = S[OFF_BRZ0 + g + 64 * i];
            gbias[1][i] = S[OFF_BRZ1 + g + 64 * i];
        }
    } else if (tid < 384) {
        int g = (tid - 256) & 31;
        #pragma unroll
        for (int i = 0; i < 4; ++i) {
            gbias[0][i] = S[OFF_BIN0 + g + 32 * i];
            gbias[1][i] = S[OFF_BIN1 + g + 32 * i];
        }
    } else {
        int g = (tid - 384) & 31;
        #pragma unroll
        for (int i = 0; i < 4; ++i) {
            gbias[0][i] = S[OFF_BHN0 + g + 32 * i];
            gbias[1][i] = S[OFF_BHN1 + g + 32 * i];
        }
    }

    // ---------------- GRU decoder + head ----------------
    const int plen = plen_p[0];
    for (int td = 0; td < plen; ++td) {
        #pragma unroll
        for (int l = 0; l < 2; ++l) {
            const int xoff = l ? 128 : 0;
            const float* grz = S + (l ? OFF_GRZ1 : OFF_GRZ0);
            const float* win = S + (l ? OFF_WIN1 : OFF_WIN0);
            const float* whn = S + (l ? OFF_WHN1 : OFF_WHN0);

            unsigned long long acc[4][4];
            #pragma unroll
            for (int i = 0; i < 4; ++i)
                #pragma unroll
                for (int j = 0; j < 4; ++j) acc[i][j] = 0ull;

            if (tid < 256) {
                int g = tid & 63, rr = (tid >> 6) << 2;
                dotKP<256, 64>(grz, g, &st[rr][xoff], acc);
                #pragma unroll
                for (int i = 0; i < 4; ++i)
                    #pragma unroll
                    for (int j = 0; j < 4; ++j)
                        gb[rr + j][g + 64 * i] = gbias[l][i] + red2(acc[i][j]);
            } else if (tid < 384) {
                int lo = tid - 256;
                int g = lo & 31, rr = (lo >> 5) << 2;
                dotKP<128, 32>(win, g, &st[rr][xoff], acc);
                #pragma unroll
                for (int i = 0; i < 4; ++i)
                    #pragma unroll
                    for (int j = 0; j < 4; ++j)
                        gb[rr + j][256 + g + 32 * i] = gbias[l][i] + red2(acc[i][j]);
            } else {
                int lo = tid - 384;
                int g = lo & 31, rr = (lo >> 5) << 2;
                dotKP<128, 32>(whn, g, &st[rr][xoff + 128], acc);
                #pragma unroll
                for (int i = 0; i < 4; ++i)
                    #pragma unroll
                    for (int j = 0; j < 4; ++j)
                        gb[rr + j][384 + g + 32 * i] = gbias[l][i] + red2(acc[i][j]);
            }
            __syncthreads();

            #pragma unroll
            for (int p = 0; p < 4; ++p) {
                int idx = tid + p * NTHREADS;
                int r = idx >> 7, d = idx & 127;
                float rv = sigf(gb[r][d]);
                float zv = sigf(gb[r][128 + d]);
                float nv = tanhfast(gb[r][256 + d] + rv * gb[r][384 + d]);
                float hold = st[r][xoff + 128 + d];
                float hnew = (1.f - zv) * nv + zv * hold;
                st[r][xoff + 128 + d] = hnew;
                if (l == 1) st[r][d] = hnew;
            }
            __syncthreads();
        }

        // head: fc1 relu -> fc2
        #pragma unroll
        for (int p = 0; p < 2; ++p) {
            int idx = tid + p * NTHREADS;   // [0, 1024)
            int r = idx >> 6, j = idx & 63;
            float acc = S[OFF_FC1B + j];
            acc = dot1<64, 32>(S + OFF_FC1, j, &st[r][256], acc);
            gb[r][j] = fmaxf(acc, 0.f);
        }
        __syncthreads();
        if (tid < 32) {
            int r = tid >> 1, o = tid & 1;
            float a = fc2bs[o];
            #pragma unroll 8
            for (int k = 0; k < 64; ++k) a = fmaf(fc2ws[o * 64 + k], gb[r][k], a);
            out[((rbase + r) * plen + td) * 2 + o] = a;
        }
        __syncthreads();
    }
}

// ---------------------------------------------------------------------------
// launch
// ---------------------------------------------------------------------------
extern "C" void kernel_launch(void* const* d_in, const int* in_sizes, int n_in,
                              void* d_out, int out_size)
{
    const float* x        = (const float*)d_in[0];
    const int*   pred_len = (const int*)  d_in[1];
    const float* wih0  = (const float*)d_in[2];
    const float* whh0  = (const float*)d_in[3];
    const float* bih0  = (const float*)d_in[4];
    const float* bhh0  = (const float*)d_in[5];
    const float* wih1  = (const float*)d_in[6];
    const float* whh1  = (const float*)d_in[7];
    const float* bih1  = (const float*)d_in[8];
    const float* bhh1  = (const float*)d_in[9];
    const float* gwih0 = (const float*)d_in[10];
    const float* gwhh0 = (const float*)d_in[11];
    const float* gbih0 = (const float*)d_in[12];
    const float* gbhh0 = (const float*)d_in[13];
    const float* gwih1 = (const float*)d_in[14];
    const float* gwhh1 = (const float*)d_in[15];
    const float* gbih1 = (const float*)d_in[16];
    const float* gbhh1 = (const float*)d_in[17];
    const float* brw   = (const float*)d_in[18];
    const float* brb   = (const float*)d_in[19];
    const float* fc1w  = (const float*)d_in[20];
    const float* fc1b  = (const float*)d_in[21];
    const float* fc2w  = (const float*)d_in[22];
    const float* fc2b  = (const float*)d_in[23];
    float* out = (float*)d_out;

    static bool attr_set = false;
    if (!attr_set) {
        cudaFuncSetAttribute(fused_kernel,
                             cudaFuncAttributeMaxDynamicSharedMemorySize, SMEM_BYTES);
        attr_set = true;
    }

    int prep_blocks = (SCRATCH_TOTAL + 255) / 256;
    prep_kernel<<<prep_blocks, 256>>>(wih0, whh0, bih0, bhh0,
                                      wih1, whh1, bih1, bhh1,
                                      gwih0, gwhh0, gbih0, gbhh0,
                                      gwih1, gwhh1, gbih1, gbhh1,
                                      brw, brb, fc1w, fc1b);
    fused_kernel<<<NBLOCKS, NTHREADS, SMEM_BYTES>>>(x, pred_len, fc2w, fc2b, out);
}

// round 4
// speedup vs baseline: 1.3242x; 1.0916x over previous
#include <cuda_runtime.h>
#include <cuda_bf16.h>

// ---------------------------------------------------------------------------
// Fused LSTM(2)->bridge->GRU(2, autoregressive)->MLP predictor.
// B=2048, H=128, S=64. 256 blocks x 8 rows, 256 threads, 2 CTAs/SM.
// Register tiling: 4 gates x 4 rows per thread; fma.rn.f32x2 packed over k.
// ---------------------------------------------------------------------------

#define NROWS 8
#define NTHREADS 256
#define NBLOCKS 256   // 2048 / 8
#define SEQ 64
#define H 128

// ----- scratch layout (floats), identical to validated layout -----
#define OFF_W0    0
#define OFF_W1    67584
#define OFF_GRZ0  198656
#define OFF_GRZ1  264192
#define OFF_WIN0  329728
#define OFF_WHN0  346112
#define OFF_WIN1  362496
#define OFF_WHN1  378880
#define OFF_BR    395264
#define OFF_FC1   411648
#define OFF_B0    419840
#define OFF_B1    420352
#define OFF_BRZ0  420864
#define OFF_BRZ1  421120
#define OFF_BIN0  421376
#define OFF_BHN0  421504
#define OFF_BIN1  421632
#define OFF_BHN1  421760
#define OFF_BB    421888
#define OFF_FC1B  422016
#define SCRATCH_TOTAL 422080

__device__ __align__(16) float g_scratch[SCRATCH_TOTAL];

// dynamic smem layout (floats)
#define SM_ST   0                 // st[8][384]
#define SM_C0   (NROWS*384)       // c0s[8][128]
#define SM_C1   (SM_C0 + NROWS*128)
#define SM_GB   (SM_C1 + NROWS*128)  // gb[8][512]
#define SM_TOTAL (SM_GB + NROWS*512) // 9216 floats = 36864 bytes
#define SMEM_BYTES (SM_TOTAL * 4)

// ---------------------------------------------------------------------------
// Prep kernel (unchanged, validated)
// ---------------------------------------------------------------------------
__global__ void prep_kernel(
    const float* __restrict__ wih0, const float* __restrict__ whh0,
    const float* __restrict__ bih0, const float* __restrict__ bhh0,
    const float* __restrict__ wih1, const float* __restrict__ whh1,
    const float* __restrict__ bih1, const float* __restrict__ bhh1,
    const float* __restrict__ gwih0, const float* __restrict__ gwhh0,
    const float* __restrict__ gbih0, const float* __restrict__ gbhh0,
    const float* __restrict__ gwih1, const float* __restrict__ gwhh1,
    const float* __restrict__ gbih1, const float* __restrict__ gbhh1,
    const float* __restrict__ brw,  const float* __restrict__ brb,
    const float* __restrict__ fc1w, const float* __restrict__ fc1b)
{
    int idx = blockIdx.x * blockDim.x + threadIdx.x;
    if (idx >= SCRATCH_TOTAL) return;
    float v = 0.0f;

    if (idx < OFF_W1) {
        int i = idx - OFF_W0;
        int kk = i & 3; int j = i >> 2; int g = j & 511; int k4 = j >> 9;
        int k = 4*k4 + kk;
        v = (k < 4) ? wih0[g*4 + k] : whh0[g*128 + (k - 4)];
    } else if (idx < OFF_GRZ0) {
        int i = idx - OFF_W1;
        int kk = i & 3; int j = i >> 2; int g = j & 511; int k4 = j >> 9;
        int k = 4*k4 + kk;
        v = (k < 128) ? wih1[g*128 + k] : whh1[g*128 + (k - 128)];
    } else if (idx < OFF_GRZ1) {
        int i = idx - OFF_GRZ0;
        int kk = i & 3; int j = i >> 2; int g = j & 255; int k4 = j >> 8;
        int k = 4*k4 + kk;
        v = (k < 128) ? gwih0[g*128 + k] : gwhh0[g*128 + (k - 128)];
    } else if (idx < OFF_WIN0) {
        int i = idx - OFF_GRZ1;
        int kk = i & 3; int j = i >> 2; int g = j & 255; int k4 = j >> 8;
        int k = 4*k4 + kk;
        v = (k < 128) ? gwih1[g*128 + k] : gwhh1[g*128 + (k - 128)];
    } else if (idx < OFF_WHN0) {
        int i = idx - OFF_WIN0;
        int kk = i & 3; int j = i >> 2; int g = j & 127; int k4 = j >> 7;
        v = gwih0[(256 + g)*128 + 4*k4 + kk];
    } else if (idx < OFF_WIN1) {
        int i = idx - OFF_WHN0;
        int kk = i & 3; int j = i >> 2; int g = j & 127; int k4 = j >> 7;
        v = gwhh0[(256 + g)*128 + 4*k4 + kk];
    } else if (idx < OFF_WHN1) {
        int i = idx - OFF_WIN1;
        int kk = i & 3; int j = i >> 2; int g = j & 127; int k4 = j >> 7;
        v = gwih1[(256 + g)*128 + 4*k4 + kk];
    } else if (idx < OFF_BR) {
        int i = idx - OFF_WHN1;
        int kk = i & 3; int j = i >> 2; int g = j & 127; int k4 = j >> 7;
        v = gwhh1[(256 + g)*128 + 4*k4 + kk];
    } else if (idx < OFF_FC1) {
        int i = idx - OFF_BR;
        int kk = i & 3; int j = i >> 2; int g = j & 127; int k4 = j >> 7;
        v = brw[g*128 + 4*k4 + kk];
    } else if (idx < OFF_B0) {
        int i = idx - OFF_FC1;
        int kk = i & 3; int j = i >> 2; int g = j & 63; int k4 = j >> 6;
        v = fc1w[g*128 + 4*k4 + kk];
    } else if (idx < OFF_B1)   { int i = idx - OFF_B0;   v = bih0[i] + bhh0[i]; }
    else if (idx < OFF_BRZ0)   { int i = idx - OFF_B1;   v = bih1[i] + bhh1[i]; }
    else if (idx < OFF_BRZ1)   { int i = idx - OFF_BRZ0; v = gbih0[i] + gbhh0[i]; }
    else if (idx < OFF_BIN0)   { int i = idx - OFF_BRZ1; v = gbih1[i] + gbhh1[i]; }
    else if (idx < OFF_BHN0)   { int i = idx - OFF_BIN0; v = gbih0[256 + i]; }
    else if (idx < OFF_BIN1)   { int i = idx - OFF_BHN0; v = gbhh0[256 + i]; }
    else if (idx < OFF_BHN1)   { int i = idx - OFF_BIN1; v = gbih1[256 + i]; }
    else if (idx < OFF_BB)     { int i = idx - OFF_BHN1; v = gbhh1[256 + i]; }
    else if (idx < OFF_FC1B)   { int i = idx - OFF_BB;   v = brb[i]; }
    else                       { int i = idx - OFF_FC1B; v = fc1b[i]; }

    g_scratch[idx] = v;
}

// ---------------------------------------------------------------------------
// Activations
// ---------------------------------------------------------------------------
__device__ __forceinline__ float sigf(float x) {
    x = fminf(fmaxf(x, -30.f), 30.f);
    return 1.f / (1.f + __expf(-x));
}
__device__ __forceinline__ float tanhfast(float x) {
    x = fminf(fmaxf(x, -15.f), 15.f);
    float e = __expf(2.f * x);
    return 1.f - 2.f / (e + 1.f);
}

// ---------------------------------------------------------------------------
// Packed f32x2 FMA
// ---------------------------------------------------------------------------
__device__ __forceinline__ void ffma2(unsigned long long& d,
                                      unsigned long long a,
                                      unsigned long long b) {
    asm("fma.rn.f32x2 %0, %1, %2, %0;" : "+l"(d) : "l"(a), "l"(b));
}
__device__ __forceinline__ float red2(unsigned long long a) {
    float lo = __uint_as_float((unsigned)(a & 0xffffffffull));
    float hi = __uint_as_float((unsigned)(a >> 32));
    return lo + hi;
}

// ---------------------------------------------------------------------------
// Tiled gate dot: 4 gates x 4 rows per thread, f32x2 packed over k.
// ---------------------------------------------------------------------------
template<int GW, int K4>
__device__ __forceinline__ void dotKP(const float* __restrict__ wbase, int g0,
                                      const float* __restrict__ stp,
                                      unsigned long long acc[4][4])
{
    const ulonglong2* wq = reinterpret_cast<const ulonglong2*>(wbase);
    #pragma unroll 4
    for (int k4 = 0; k4 < K4; ++k4) {
        ulonglong2 w[4];
        #pragma unroll
        for (int i = 0; i < 4; ++i)
            w[i] = __ldg(&wq[k4 * GW + g0 + i * (GW / 4)]);
        #pragma unroll
        for (int j = 0; j < 4; ++j) {
            ulonglong2 s = *reinterpret_cast<const ulonglong2*>(stp + j * 384 + 4 * k4);
            #pragma unroll
            for (int i = 0; i < 4; ++i) {
                ffma2(acc[i][j], w[i].x, s.x);
                ffma2(acc[i][j], w[i].y, s.y);
            }
        }
    }
}

// scalar single-row dot (bridge / fc1)
template<int GW, int K4>
__device__ __forceinline__ float dot1(const float* __restrict__ wbase, int g,
                                      const float* __restrict__ srow, float acc)
{
    const float4* w4 = reinterpret_cast<const float4*>(wbase);
    const float4* s4 = reinterpret_cast<const float4*>(srow);
    #pragma unroll 4
    for (int k4 = 0; k4 < K4; ++k4) {
        float4 w = __ldg(&w4[k4 * GW + g]);
        float4 s = s4[k4];
        acc = fmaf(w.x, s.x, acc);
        acc = fmaf(w.y, s.y, acc);
        acc = fmaf(w.z, s.z, acc);
        acc = fmaf(w.w, s.w, acc);
    }
    return acc;
}

// ---------------------------------------------------------------------------
// Main fused kernel: 256 threads, 8 rows, 2 CTAs per SM
// ---------------------------------------------------------------------------
__global__ void __launch_bounds__(NTHREADS, 2)
fused_kernel(const float* __restrict__ x, const int* __restrict__ plen_p,
             const float* __restrict__ fc2w, const float* __restrict__ fc2b,
             float* __restrict__ out)
{
    extern __shared__ float sm[];
    float (*st)[384]  = (float (*)[384])(sm + SM_ST);
    float (*c0s)[128] = (float (*)[128])(sm + SM_C0);
    float (*c1s)[128] = (float (*)[128])(sm + SM_C1);
    float (*gb)[512]  = (float (*)[512])(sm + SM_GB);
    __shared__ float fc2ws[128];
    __shared__ float fc2bs[2];

    const int tid = threadIdx.x;
    const int rbase = blockIdx.x * NROWS;
    const float* S = g_scratch;

    for (int i = tid; i < SM_TOTAL; i += NTHREADS) sm[i] = 0.f;
    if (tid < 128) fc2ws[tid] = fc2w[tid];
    if (tid < 2) fc2bs[tid] = fc2b[tid];
    __syncthreads();

    // LSTM mapping: gq in [0,128), rq4 in {0,4}
    const int gq  = tid & 127;
    const int rq4 = (tid >> 7) << 2;
    float bl0[4], bl1[4];
    #pragma unroll
    for (int i = 0; i < 4; ++i) {
        bl0[i] = S[OFF_B0 + gq + 128 * i];
        bl1[i] = S[OFF_B1 + gq + 128 * i];
    }

    // ---------------- LSTM encoder ----------------
    for (int t = 0; t < SEQ; ++t) {
        if (tid < 32) {
            int r = tid >> 2, k = tid & 3;
            st[r][k] = x[((rbase + r) * SEQ + t) * 4 + k];
        }
        __syncthreads();

        // layer 0: [x;h0], K=132
        {
            unsigned long long acc[4][4];
            #pragma unroll
            for (int i = 0; i < 4; ++i)
                #pragma unroll
                for (int j = 0; j < 4; ++j) acc[i][j] = 0ull;
            dotKP<512, 33>(S + OFF_W0, gq, &st[rq4][0], acc);
            #pragma unroll
            for (int i = 0; i < 4; ++i)
                #pragma unroll
                for (int j = 0; j < 4; ++j)
                    gb[rq4 + j][gq + 128 * i] = bl0[i] + red2(acc[i][j]);
        }
        __syncthreads();
        #pragma unroll
        for (int p = 0; p < 4; ++p) {
            int idx = tid + p * NTHREADS;        // [0, 1024)
            int r = idx >> 7, d = idx & 127;
            float gi = sigf(gb[r][d]);
            float gf = sigf(gb[r][128 + d]);
            float gg = tanhfast(gb[r][256 + d]);
            float go = sigf(gb[r][384 + d]);
            float cn = gf * c0s[r][d] + gi * gg;
            c0s[r][d] = cn;
            st[r][4 + d] = go * tanhfast(cn);
        }
        __syncthreads();

        // layer 1: [h0;h1], K=256 (offset 4)
        {
            unsigned long long acc[4][4];
            #pragma unroll
            for (int i = 0; i < 4; ++i)
                #pragma unroll
                for (int j = 0; j < 4; ++j) acc[i][j] = 0ull;
            dotKP<512, 64>(S + OFF_W1, gq, &st[rq4][4], acc);
            #pragma unroll
            for (int i = 0; i < 4; ++i)
                #pragma unroll
                for (int j = 0; j < 4; ++j)
                    gb[rq4 + j][gq + 128 * i] = bl1[i] + red2(acc[i][j]);
        }
        __syncthreads();
        #pragma unroll
        for (int p = 0; p < 4; ++p) {
            int idx = tid + p * NTHREADS;
            int r = idx >> 7, d = idx & 127;
            float gi = sigf(gb[r][d]);
            float gf = sigf(gb[r][128 + d]);
            float gg = tanhfast(gb[r][256 + d]);
            float go = sigf(gb[r][384 + d]);
            float cn = gf * c1s[r][d] + gi * gg;
            c1s[r][d] = cn;
            st[r][132 + d] = go * tanhfast(cn);
        }
        __syncthreads();
    }

    // ---------------- bridge ----------------
    #pragma unroll
    for (int p = 0; p < 8; ++p) {
        int idx = tid + p * NTHREADS;          // [0, 2048)
        int l = idx >> 10;
        int rem = idx & 1023;
        int r = rem >> 7, d = rem & 127;
        float acc = S[OFF_BB + d];
        acc = dot1<128, 32>(S + OFF_BR, d, &st[r][4 + 128 * l], acc);
        gb[r][l * 128 + d] = tanhfast(acc);
    }
    __syncthreads();
    // restage: inp = h1(final), hd0 = hg0, hd1 = hg1
    {
        float inpv[4], g0v[4], g1v[4];
        #pragma unroll
        for (int p = 0; p < 4; ++p) {
            int idx = tid + p * NTHREADS;      // [0, 1024)
            int r = idx >> 7, d = idx & 127;
            inpv[p] = st[r][132 + d];
            g0v[p] = gb[r][d];
            g1v[p] = gb[r][128 + d];
        }
        __syncthreads();
        #pragma unroll
        for (int p = 0; p < 4; ++p) {
            int idx = tid + p * NTHREADS;
            int r = idx >> 7, d = idx & 127;
            st[r][d] = inpv[p];
            st[r][128 + d] = g0v[p];
            st[r][256 + d] = g1v[p];
        }
    }
    __syncthreads();

    // GRU per-role bias preload
    // roles: tid<128: rz (GW=256); tid<192: n-in (GW=128); else: n-hid
    float gbias[2][4];
    if (tid < 128) {
        int g = tid & 63;
        #pragma unroll
        for (int i = 0; i < 4; ++i) {
            gbias[0][i] = S[OFF_BRZ0 + g + 64 * i];
            gbias[1][i] = S[OFF_BRZ1 + g + 64 * i];
        }
    } else if (tid < 192) {
        int g = (tid - 128) & 31;
        #pragma unroll
        for (int i = 0; i < 4; ++i) {
            gbias[0][i] = S[OFF_BIN0 + g + 32 * i];
            gbias[1][i] = S[OFF_BIN1 + g + 32 * i];
        }
    } else {
        int g = (tid - 192) & 31;
        #pragma unroll
        for (int i = 0; i < 4; ++i) {
            gbias[0][i] = S[OFF_BHN0 + g + 32 * i];
            gbias[1][i] = S[OFF_BHN1 + g + 32 * i];
        }
    }

    // ---------------- GRU decoder + head ----------------
    const int plen = plen_p[0];
    for (int td = 0; td < plen; ++td) {
        #pragma unroll
        for (int l = 0; l < 2; ++l) {
            const int xoff = l ? 128 : 0;
            const float* grz = S + (l ? OFF_GRZ1 : OFF_GRZ0);
            const float* win = S + (l ? OFF_WIN1 : OFF_WIN0);
            const float* whn = S + (l ? OFF_WHN1 : OFF_WHN0);

            unsigned long long acc[4][4];
            #pragma unroll
            for (int i = 0; i < 4; ++i)
                #pragma unroll
                for (int j = 0; j < 4; ++j) acc[i][j] = 0ull;

            if (tid < 128) {
                int g = tid & 63, rr = (tid >> 6) << 2;
                dotKP<256, 64>(grz, g, &st[rr][xoff], acc);
                #pragma unroll
                for (int i = 0; i < 4; ++i)
                    #pragma unroll
                    for (int j = 0; j < 4; ++j)
                        gb[rr + j][g + 64 * i] = gbias[l][i] + red2(acc[i][j]);
            } else if (tid < 192) {
                int lo = tid - 128;
                int g = lo & 31, rr = (lo >> 5) << 2;
                dotKP<128, 32>(win, g, &st[rr][xoff], acc);
                #pragma unroll
                for (int i = 0; i < 4; ++i)
                    #pragma unroll
                    for (int j = 0; j < 4; ++j)
                        gb[rr + j][256 + g + 32 * i] = gbias[l][i] + red2(acc[i][j]);
            } else {
                int lo = tid - 192;
                int g = lo & 31, rr = (lo >> 5) << 2;
                dotKP<128, 32>(whn, g, &st[rr][xoff + 128], acc);
                #pragma unroll
                for (int i = 0; i < 4; ++i)
                    #pragma unroll
                    for (int j = 0; j < 4; ++j)
                        gb[rr + j][384 + g + 32 * i] = gbias[l][i] + red2(acc[i][j]);
            }
            __syncthreads();

            #pragma unroll
            for (int p = 0; p < 4; ++p) {
                int idx = tid + p * NTHREADS;   // [0, 1024)
                int r = idx >> 7, d = idx & 127;
                float rv = sigf(gb[r][d]);
                float zv = sigf(gb[r][128 + d]);
                float nv = tanhfast(gb[r][256 + d] + rv * gb[r][384 + d]);
                float hold = st[r][xoff + 128 + d];
                float hnew = (1.f - zv) * nv + zv * hold;
                st[r][xoff + 128 + d] = hnew;
                if (l == 1) st[r][d] = hnew;
            }
            __syncthreads();
        }

        // head: fc1 relu -> fc2
        #pragma unroll
        for (int p = 0; p < 2; ++p) {
            int idx = tid + p * NTHREADS;   // [0, 512)
            int r = idx >> 6, j = idx & 63;
            float acc = S[OFF_FC1B + j];
            acc = dot1<64, 32>(S + OFF_FC1, j, &st[r][256], acc);
            gb[r][j] = fmaxf(acc, 0.f);
        }
        __syncthreads();
        if (tid < 16) {
            int r = tid >> 1, o = tid & 1;
            float a = fc2bs[o];
            #pragma unroll 8
            for (int k = 0; k < 64; ++k) a = fmaf(fc2ws[o * 64 + k], gb[r][k], a);
            out[((rbase + r) * plen + td) * 2 + o] = a;
        }
        __syncthreads();
    }
}

// ---------------------------------------------------------------------------
// launch
// ---------------------------------------------------------------------------
extern "C" void kernel_launch(void* const* d_in, const int* in_sizes, int n_in,
                              void* d_out, int out_size)
{
    const float* x        = (const float*)d_in[0];
    const int*   pred_len = (const int*)  d_in[1];
    const float* wih0  = (const float*)d_in[2];
    const float* whh0  = (const float*)d_in[3];
    const float* bih0  = (const float*)d_in[4];
    const float* bhh0  = (const float*)d_in[5];
    const float* wih1  = (const float*)d_in[6];
    const float* whh1  = (const float*)d_in[7];
    const float* bih1  = (const float*)d_in[8];
    const float* bhh1  = (const float*)d_in[9];
    const float* gwih0 = (const float*)d_in[10];
    const float* gwhh0 = (const float*)d_in[11];
    const float* gbih0 = (const float*)d_in[12];
    const float* gbhh0 = (const float*)d_in[13];
    const float* gwih1 = (const float*)d_in[14];
    const float* gwhh1 = (const float*)d_in[15];
    const float* gbih1 = (const float*)d_in[16];
    const float* gbhh1 = (const float*)d_in[17];
    const float* brw   = (const float*)d_in[18];
    const float* brb   = (const float*)d_in[19];
    const float* fc1w  = (const float*)d_in[20];
    const float* fc1b  = (const float*)d_in[21];
    const float* fc2w  = (const float*)d_in[22];
    const float* fc2b  = (const float*)d_in[23];
    float* out = (float*)d_out;

    static bool attr_set = false;
    if (!attr_set) {
        cudaFuncSetAttribute(fused_kernel,
                             cudaFuncAttributeMaxDynamicSharedMemorySize, SMEM_BYTES);
        attr_set = true;
    }

    int prep_blocks = (SCRATCH_TOTAL + 255) / 256;
    prep_kernel<<<prep_blocks, 256>>>(wih0, whh0, bih0, bhh0,
                                      wih1, whh1, bih1, bhh1,
                                      gwih0, gwhh0, gbih0, gbhh0,
                                      gwih1, gwhh1, gbih1, gbhh1,
                                      brw, brb, fc1w, fc1b);
    fused_kernel<<<NBLOCKS, NTHREADS, SMEM_BYTES>>>(x, pred_len, fc2w, fc2b, out);
}

// round 5
// speedup vs baseline: 1.3711x; 1.0354x over previous
#include <cuda_runtime.h>
#include <cuda_bf16.h>

// ---------------------------------------------------------------------------
// Fused LSTM(2)->bridge->GRU(2, autoregressive)->MLP predictor.
// B=2048, H=128, S=64. 256 blocks x 8 rows, 256 threads, 2 CTAs/SM.
// LSTM layer-wavefront (l0(t) + l1(t-1) in one phase); GRU n-gates fused
// in/hn per thread + MLP head folded into gate phases; fast-math divisions.
// ---------------------------------------------------------------------------

#define NROWS 8
#define NTHREADS 256
#define NBLOCKS 256   // 2048 / 8
#define SEQ 64
#define H 128

// ----- scratch layout (floats), identical to validated layout -----
#define OFF_W0    0
#define OFF_W1    67584
#define OFF_GRZ0  198656
#define OFF_GRZ1  264192
#define OFF_WIN0  329728
#define OFF_WHN0  346112
#define OFF_WIN1  362496
#define OFF_WHN1  378880
#define OFF_BR    395264
#define OFF_FC1   411648
#define OFF_B0    419840
#define OFF_B1    420352
#define OFF_BRZ0  420864
#define OFF_BRZ1  421120
#define OFF_BIN0  421376
#define OFF_BHN0  421504
#define OFF_BIN1  421632
#define OFF_BHN1  421760
#define OFF_BB    421888
#define OFF_FC1B  422016
#define SCRATCH_TOTAL 422080

__device__ __align__(16) float g_scratch[SCRATCH_TOTAL];

// dynamic smem layout (floats)
#define SM_ST   0                     // st[8][384]
#define SM_C0   (NROWS*384)           // c0s[8][128]
#define SM_C1   (SM_C0 + NROWS*128)   // c1s[8][128]
#define SM_GB0  (SM_C1 + NROWS*128)   // gb0[8][512]
#define SM_GB1  (SM_GB0 + NROWS*512)  // gb1[8][512]
#define SM_XS   (SM_GB1 + NROWS*512)  // xs[8][256]
#define SM_GBH  (SM_XS + NROWS*256)   // gbH[8][64]
#define SM_TOTAL (SM_GBH + NROWS*64)  // 15872 floats = 63488 bytes
#define SMEM_BYTES (SM_TOTAL * 4)

// ---------------------------------------------------------------------------
// Prep kernel (unchanged, validated)
// ---------------------------------------------------------------------------
__global__ void prep_kernel(
    const float* __restrict__ wih0, const float* __restrict__ whh0,
    const float* __restrict__ bih0, const float* __restrict__ bhh0,
    const float* __restrict__ wih1, const float* __restrict__ whh1,
    const float* __restrict__ bih1, const float* __restrict__ bhh1,
    const float* __restrict__ gwih0, const float* __restrict__ gwhh0,
    const float* __restrict__ gbih0, const float* __restrict__ gbhh0,
    const float* __restrict__ gwih1, const float* __restrict__ gwhh1,
    const float* __restrict__ gbih1, const float* __restrict__ gbhh1,
    const float* __restrict__ brw,  const float* __restrict__ brb,
    const float* __restrict__ fc1w, const float* __restrict__ fc1b)
{
    int idx = blockIdx.x * blockDim.x + threadIdx.x;
    if (idx >= SCRATCH_TOTAL) return;
    float v = 0.0f;

    if (idx < OFF_W1) {
        int i = idx - OFF_W0;
        int kk = i & 3; int j = i >> 2; int g = j & 511; int k4 = j >> 9;
        int k = 4*k4 + kk;
        v = (k < 4) ? wih0[g*4 + k] : whh0[g*128 + (k - 4)];
    } else if (idx < OFF_GRZ0) {
        int i = idx - OFF_W1;
        int kk = i & 3; int j = i >> 2; int g = j & 511; int k4 = j >> 9;
        int k = 4*k4 + kk;
        v = (k < 128) ? wih1[g*128 + k] : whh1[g*128 + (k - 128)];
    } else if (idx < OFF_GRZ1) {
        int i = idx - OFF_GRZ0;
        int kk = i & 3; int j = i >> 2; int g = j & 255; int k4 = j >> 8;
        int k = 4*k4 + kk;
        v = (k < 128) ? gwih0[g*128 + k] : gwhh0[g*128 + (k - 128)];
    } else if (idx < OFF_WIN0) {
        int i = idx - OFF_GRZ1;
        int kk = i & 3; int j = i >> 2; int g = j & 255; int k4 = j >> 8;
        int k = 4*k4 + kk;
        v = (k < 128) ? gwih1[g*128 + k] : gwhh1[g*128 + (k - 128)];
    } else if (idx < OFF_WHN0) {
        int i = idx - OFF_WIN0;
        int kk = i & 3; int j = i >> 2; int g = j & 127; int k4 = j >> 7;
        v = gwih0[(256 + g)*128 + 4*k4 + kk];
    } else if (idx < OFF_WIN1) {
        int i = idx - OFF_WHN0;
        int kk = i & 3; int j = i >> 2; int g = j & 127; int k4 = j >> 7;
        v = gwhh0[(256 + g)*128 + 4*k4 + kk];
    } else if (idx < OFF_WHN1) {
        int i = idx - OFF_WIN1;
        int kk = i & 3; int j = i >> 2; int g = j & 127; int k4 = j >> 7;
        v = gwih1[(256 + g)*128 + 4*k4 + kk];
    } else if (idx < OFF_BR) {
        int i = idx - OFF_WHN1;
        int kk = i & 3; int j = i >> 2; int g = j & 127; int k4 = j >> 7;
        v = gwhh1[(256 + g)*128 + 4*k4 + kk];
    } else if (idx < OFF_FC1) {
        int i = idx - OFF_BR;
        int kk = i & 3; int j = i >> 2; int g = j & 127; int k4 = j >> 7;
        v = brw[g*128 + 4*k4 + kk];
    } else if (idx < OFF_B0) {
        int i = idx - OFF_FC1;
        int kk = i & 3; int j = i >> 2; int g = j & 63; int k4 = j >> 6;
        v = fc1w[g*128 + 4*k4 + kk];
    } else if (idx < OFF_B1)   { int i = idx - OFF_B0;   v = bih0[i] + bhh0[i]; }
    else if (idx < OFF_BRZ0)   { int i = idx - OFF_B1;   v = bih1[i] + bhh1[i]; }
    else if (idx < OFF_BRZ1)   { int i = idx - OFF_BRZ0; v = gbih0[i] + gbhh0[i]; }
    else if (idx < OFF_BIN0)   { int i = idx - OFF_BRZ1; v = gbih1[i] + gbhh1[i]; }
    else if (idx < OFF_BHN0)   { int i = idx - OFF_BIN0; v = gbih0[256 + i]; }
    else if (idx < OFF_BIN1)   { int i = idx - OFF_BHN0; v = gbhh0[256 + i]; }
    else if (idx < OFF_BHN1)   { int i = idx - OFF_BIN1; v = gbih1[256 + i]; }
    else if (idx < OFF_BB)     { int i = idx - OFF_BHN1; v = gbhh1[256 + i]; }
    else if (idx < OFF_FC1B)   { int i = idx - OFF_BB;   v = brb[i]; }
    else                       { int i = idx - OFF_FC1B; v = fc1b[i]; }

    g_scratch[idx] = v;
}

// ---------------------------------------------------------------------------
// Activations (fast-math: MUFU-based exp + approximate reciprocal)
// ---------------------------------------------------------------------------
__device__ __forceinline__ float sigf(float x) {
    x = fminf(fmaxf(x, -30.f), 30.f);
    return __fdividef(1.f, 1.f + __expf(-x));
}
__device__ __forceinline__ float tanhfast(float x) {
    x = fminf(fmaxf(x, -15.f), 15.f);
    float e = __expf(2.f * x);
    return 1.f - __fdividef(2.f, e + 1.f);
}

// ---------------------------------------------------------------------------
// Packed f32x2 FMA
// ---------------------------------------------------------------------------
__device__ __forceinline__ void ffma2(unsigned long long& d,
                                      unsigned long long a,
                                      unsigned long long b) {
    asm("fma.rn.f32x2 %0, %1, %2, %0;" : "+l"(d) : "l"(a), "l"(b));
}
__device__ __forceinline__ float red2(unsigned long long a) {
    float lo = __uint_as_float((unsigned)(a & 0xffffffffull));
    float hi = __uint_as_float((unsigned)(a >> 32));
    return lo + hi;
}

// ---------------------------------------------------------------------------
// Generalized tiled dot: NG gates (stride GW/NG) x 4 rows, f32x2 over k.
// ---------------------------------------------------------------------------
template<int NG, int GW, int K4>
__device__ __forceinline__ void dotG(const float* __restrict__ wbase, int g0,
                                     const float* __restrict__ stp,
                                     unsigned long long acc[NG][4])
{
    const ulonglong2* wq = reinterpret_cast<const ulonglong2*>(wbase);
    #pragma unroll 4
    for (int k4 = 0; k4 < K4; ++k4) {
        ulonglong2 w[NG];
        #pragma unroll
        for (int i = 0; i < NG; ++i)
            w[i] = __ldg(&wq[k4 * GW + g0 + i * (GW / NG)]);
        #pragma unroll
        for (int j = 0; j < 4; ++j) {
            ulonglong2 s = *reinterpret_cast<const ulonglong2*>(stp + j * 384 + 4 * k4);
            #pragma unroll
            for (int i = 0; i < NG; ++i) {
                ffma2(acc[i][j], w[i].x, s.x);
                ffma2(acc[i][j], w[i].y, s.y);
            }
        }
    }
}

// scalar single-row dot (bridge)
template<int GW, int K4>
__device__ __forceinline__ float dot1(const float* __restrict__ wbase, int g,
                                      const float* __restrict__ srow, float acc)
{
    const float4* w4 = reinterpret_cast<const float4*>(wbase);
    const float4* s4 = reinterpret_cast<const float4*>(srow);
    #pragma unroll 4
    for (int k4 = 0; k4 < K4; ++k4) {
        float4 w = __ldg(&w4[k4 * GW + g]);
        float4 s = s4[k4];
        acc = fmaf(w.x, s.x, acc);
        acc = fmaf(w.y, s.y, acc);
        acc = fmaf(w.z, s.z, acc);
        acc = fmaf(w.w, s.w, acc);
    }
    return acc;
}

// ---------------------------------------------------------------------------
// Main fused kernel
// ---------------------------------------------------------------------------
__global__ void __launch_bounds__(NTHREADS, 2)
fused_kernel(const float* __restrict__ x, const int* __restrict__ plen_p,
             const float* __restrict__ fc2w, const float* __restrict__ fc2b,
             float* __restrict__ out)
{
    extern __shared__ float sm[];
    float (*st)[384]  = (float (*)[384])(sm + SM_ST);
    float (*c0s)[128] = (float (*)[128])(sm + SM_C0);
    float (*c1s)[128] = (float (*)[128])(sm + SM_C1);
    float (*gb0)[512] = (float (*)[512])(sm + SM_GB0);
    float (*gb1)[512] = (float (*)[512])(sm + SM_GB1);
    float (*xs)[256]  = (float (*)[256])(sm + SM_XS);
    float (*gbH)[64]  = (float (*)[64])(sm + SM_GBH);
    __shared__ float fc2ws[128];
    __shared__ float fc2bs[2];

    const int tid = threadIdx.x;
    const int rbase = blockIdx.x * NROWS;
    const float* S = g_scratch;
    const int plen = plen_p[0];

    // init: zero state, preload x block (8 rows x 256 floats, coalesced), fc2
    for (int i = tid; i < NROWS * 384; i += NTHREADS) (&st[0][0])[i] = 0.f;
    for (int i = tid; i < NROWS * 128; i += NTHREADS) { (&c0s[0][0])[i] = 0.f; (&c1s[0][0])[i] = 0.f; }
    #pragma unroll
    for (int p = 0; p < 8; ++p) {
        int idx = tid + p * NTHREADS;          // [0, 2048)
        int r = idx >> 8, off = idx & 255;
        xs[r][off] = x[(rbase + r) * 256 + off];
    }
    if (tid < 128) fc2ws[tid] = fc2w[tid];
    if (tid < 2) fc2bs[tid] = fc2b[tid];
    __syncthreads();
    // stage x(0)
    if (tid < 32) {
        int r = tid >> 2, k = tid & 3;
        st[r][k] = xs[r][k];
    }
    __syncthreads();

    // LSTM mapping: gq in [0,128), rq4 in {0,4}
    const int gq  = tid & 127;
    const int rq4 = (tid >> 7) << 2;
    float bl0[4], bl1[4];
    #pragma unroll
    for (int i = 0; i < 4; ++i) {
        bl0[i] = S[OFF_B0 + gq + 128 * i];
        bl1[i] = S[OFF_B1 + gq + 128 * i];
    }

    // ---------------- LSTM encoder: layer wavefront ----------------
    // Phase t (t=0..SEQ): gates l0(t) [t<SEQ] and l1(t-1) [t>0] together.
    for (int t = 0; t <= SEQ; ++t) {
        {
            unsigned long long acc[4][4];
            if (t < SEQ) {
                #pragma unroll
                for (int i = 0; i < 4; ++i)
                    #pragma unroll
                    for (int j = 0; j < 4; ++j) acc[i][j] = 0ull;
                dotG<4, 512, 33>(S + OFF_W0, gq, &st[rq4][0], acc);
                #pragma unroll
                for (int i = 0; i < 4; ++i)
                    #pragma unroll
                    for (int j = 0; j < 4; ++j)
                        gb0[rq4 + j][gq + 128 * i] = bl0[i] + red2(acc[i][j]);
            }
            if (t > 0) {
                #pragma unroll
                for (int i = 0; i < 4; ++i)
                    #pragma unroll
                    for (int j = 0; j < 4; ++j) acc[i][j] = 0ull;
                dotG<4, 512, 64>(S + OFF_W1, gq, &st[rq4][4], acc);
                #pragma unroll
                for (int i = 0; i < 4; ++i)
                    #pragma unroll
                    for (int j = 0; j < 4; ++j)
                        gb1[rq4 + j][gq + 128 * i] = bl1[i] + red2(acc[i][j]);
            }
        }
        __syncthreads();

        // updates: h0(t) [t<SEQ], h1(t-1) [t>0], stage x(t+1)
        if (t < SEQ) {
            #pragma unroll
            for (int p = 0; p < 4; ++p) {
                int idx = tid + p * NTHREADS;        // [0, 1024)
                int r = idx >> 7, d = idx & 127;
                float gi = sigf(gb0[r][d]);
                float gf = sigf(gb0[r][128 + d]);
                float gg = tanhfast(gb0[r][256 + d]);
                float go = sigf(gb0[r][384 + d]);
                float cn = gf * c0s[r][d] + gi * gg;
                c0s[r][d] = cn;
                st[r][4 + d] = go * tanhfast(cn);
            }
        }
        if (t > 0) {
            #pragma unroll
            for (int p = 0; p < 4; ++p) {
                int idx = tid + p * NTHREADS;
                int r = idx >> 7, d = idx & 127;
                float gi = sigf(gb1[r][d]);
                float gf = sigf(gb1[r][128 + d]);
                float gg = tanhfast(gb1[r][256 + d]);
                float go = sigf(gb1[r][384 + d]);
                float cn = gf * c1s[r][d] + gi * gg;
                c1s[r][d] = cn;
                st[r][132 + d] = go * tanhfast(cn);
            }
        }
        if (t + 1 < SEQ && tid < 32) {
            int r = tid >> 2, k = tid & 3;
            st[r][k] = xs[r][(t + 1) * 4 + k];
        }
        __syncthreads();
    }

    // ---------------- bridge ----------------
    #pragma unroll
    for (int p = 0; p < 8; ++p) {
        int idx = tid + p * NTHREADS;          // [0, 2048)
        int l = idx >> 10;
        int rem = idx & 1023;
        int r = rem >> 7, d = rem & 127;
        float acc = S[OFF_BB + d];
        acc = dot1<128, 32>(S + OFF_BR, d, &st[r][4 + 128 * l], acc);
        gb0[r][l * 128 + d] = tanhfast(acc);
    }
    __syncthreads();
    // restage: inp = h1(final), hd0 = hg0, hd1 = hg1
    {
        float inpv[4], g0v[4], g1v[4];
        #pragma unroll
        for (int p = 0; p < 4; ++p) {
            int idx = tid + p * NTHREADS;      // [0, 1024)
            int r = idx >> 7, d = idx & 127;
            inpv[p] = st[r][132 + d];
            g0v[p] = gb0[r][d];
            g1v[p] = gb0[r][128 + d];
        }
        __syncthreads();
        #pragma unroll
        for (int p = 0; p < 4; ++p) {
            int idx = tid + p * NTHREADS;
            int r = idx >> 7, d = idx & 127;
            st[r][d] = inpv[p];
            st[r][128 + d] = g0v[p];
            st[r][256 + d] = g1v[p];
        }
    }
    __syncthreads();

    // GRU roles:
    //  tid <128       : rz gates, 4g x 4r, K4=64       (g = tid&63, rr = (tid>>6)<<2)
    //  tid 128..191   : n gates (in + hn fused), 4g x 4r, K4=32+32
    //  tid 192..255   : fc1 head of previous step, 2o x 4r, K4=32
    const int role = (tid < 128) ? 0 : (tid < 192) ? 1 : 2;
    int rg = 0, rr = 0;
    float gbA[2][4], gbB[2][4];
    if (role == 0) {
        rg = tid & 63; rr = ((tid >> 6) & 1) << 2;
        #pragma unroll
        for (int i = 0; i < 4; ++i) {
            gbA[0][i] = S[OFF_BRZ0 + rg + 64 * i];
            gbA[1][i] = S[OFF_BRZ1 + rg + 64 * i];
        }
    } else if (role == 1) {
        int lo = tid - 128;
        rg = lo & 31; rr = ((lo >> 5) & 1) << 2;
        #pragma unroll
        for (int i = 0; i < 4; ++i) {
            gbA[0][i] = S[OFF_BIN0 + rg + 32 * i];
            gbA[1][i] = S[OFF_BIN1 + rg + 32 * i];
            gbB[0][i] = S[OFF_BHN0 + rg + 32 * i];
            gbB[1][i] = S[OFF_BHN1 + rg + 32 * i];
        }
    } else {
        int lo = tid - 192;
        rg = lo & 31; rr = ((lo >> 5) & 1) << 2;
        gbA[0][0] = S[OFF_FC1B + rg];
        gbA[0][1] = S[OFF_FC1B + rg + 32];
    }

    // ---------------- GRU decoder + folded head ----------------
    // td = 0..plen: GRU step td (guard td<plen), head for td-1 (guard td>0).
    for (int td = 0; td <= plen; ++td) {
        // --- phase G0: layer-0 gates + fc1(td-1) ---
        if (role == 0) {
            if (td < plen) {
                unsigned long long acc[4][4];
                #pragma unroll
                for (int i = 0; i < 4; ++i)
                    #pragma unroll
                    for (int j = 0; j < 4; ++j) acc[i][j] = 0ull;
                dotG<4, 256, 64>(S + OFF_GRZ0, rg, &st[rr][0], acc);
                #pragma unroll
                for (int i = 0; i < 4; ++i)
                    #pragma unroll
                    for (int j = 0; j < 4; ++j)
                        gb0[rr + j][rg + 64 * i] = gbA[0][i] + red2(acc[i][j]);
            }
        } else if (role == 1) {
            if (td < plen) {
                unsigned long long acc[4][4];
                #pragma unroll
                for (int i = 0; i < 4; ++i)
                    #pragma unroll
                    for (int j = 0; j < 4; ++j) acc[i][j] = 0ull;
                dotG<4, 128, 32>(S + OFF_WIN0, rg, &st[rr][0], acc);
                #pragma unroll
                for (int i = 0; i < 4; ++i)
                    #pragma unroll
                    for (int j = 0; j < 4; ++j)
                        gb0[rr + j][256 + rg + 32 * i] = gbA[0][i] + red2(acc[i][j]);
                #pragma unroll
                for (int i = 0; i < 4; ++i)
                    #pragma unroll
                    for (int j = 0; j < 4; ++j) acc[i][j] = 0ull;
                dotG<4, 128, 32>(S + OFF_WHN0, rg, &st[rr][128], acc);
                #pragma unroll
                for (int i = 0; i < 4; ++i)
                    #pragma unroll
                    for (int j = 0; j < 4; ++j)
                        gb0[rr + j][384 + rg + 32 * i] = gbB[0][i] + red2(acc[i][j]);
            }
        } else {
            if (td > 0) {
                // fc1 for step td-1 from h1(td-1) in st[.][256..383]
                unsigned long long acc[2][4];
                #pragma unroll
                for (int i = 0; i < 2; ++i)
                    #pragma unroll
                    for (int j = 0; j < 4; ++j) acc[i][j] = 0ull;
                dotG<2, 64, 32>(S + OFF_FC1, rg, &st[rr][256], acc);
                #pragma unroll
                for (int i = 0; i < 2; ++i)
                    #pragma unroll
                    for (int j = 0; j < 4; ++j)
                        gbH[rr + j][rg + 32 * i] = fmaxf(gbA[0][i] + red2(acc[i][j]), 0.f);
            }
        }
        __syncthreads();

        // --- update h0 ---
        if (td < plen) {
            #pragma unroll
            for (int p = 0; p < 4; ++p) {
                int idx = tid + p * NTHREADS;   // [0, 1024)
                int r = idx >> 7, d = idx & 127;
                float rv = sigf(gb0[r][d]);
                float zv = sigf(gb0[r][128 + d]);
                float nv = tanhfast(gb0[r][256 + d] + rv * gb0[r][384 + d]);
                float hold = st[r][128 + d];
                st[r][128 + d] = (1.f - zv) * nv + zv * hold;
            }
        }
        __syncthreads();

        // --- phase G1: layer-1 gates + fc2(td-1) + store ---
        if (role == 0) {
            if (td < plen) {
                unsigned long long acc[4][4];
                #pragma unroll
                for (int i = 0; i < 4; ++i)
                    #pragma unroll
                    for (int j = 0; j < 4; ++j) acc[i][j] = 0ull;
                dotG<4, 256, 64>(S + OFF_GRZ1, rg, &st[rr][128], acc);
                #pragma unroll
                for (int i = 0; i < 4; ++i)
                    #pragma unroll
                    for (int j = 0; j < 4; ++j)
                        gb0[rr + j][rg + 64 * i] = gbA[1][i] + red2(acc[i][j]);
            }
        } else if (role == 1) {
            if (td < plen) {
                unsigned long long acc[4][4];
                #pragma unroll
                for (int i = 0; i < 4; ++i)
                    #pragma unroll
                    for (int j = 0; j < 4; ++j) acc[i][j] = 0ull;
                dotG<4, 128, 32>(S + OFF_WIN1, rg, &st[rr][128], acc);
                #pragma unroll
                for (int i = 0; i < 4; ++i)
                    #pragma unroll
                    for (int j = 0; j < 4; ++j)
                        gb0[rr + j][256 + rg + 32 * i] = gbA[1][i] + red2(acc[i][j]);
                #pragma unroll
                for (int i = 0; i < 4; ++i)
                    #pragma unroll
                    for (int j = 0; j < 4; ++j) acc[i][j] = 0ull;
                dotG<4, 128, 32>(S + OFF_WHN1, rg, &st[rr][256], acc);
                #pragma unroll
                for (int i = 0; i < 4; ++i)
                    #pragma unroll
                    for (int j = 0; j < 4; ++j)
                        gb0[rr + j][384 + rg + 32 * i] = gbB[1][i] + red2(acc[i][j]);
            }
        } else {
            if (td > 0 && (tid - 192) < 16) {
                int lo = tid - 192;
                int r = lo >> 1, o = lo & 1;
                float a = fc2bs[o];
                #pragma unroll 8
                for (int k = 0; k < 64; ++k) a = fmaf(fc2ws[o * 64 + k], gbH[r][k], a);
                out[((rbase + r) * plen + (td - 1)) * 2 + o] = a;
            }
        }
        __syncthreads();

        // --- update h1, write next inp ---
        if (td < plen) {
            #pragma unroll
            for (int p = 0; p < 4; ++p) {
                int idx = tid + p * NTHREADS;
                int r = idx >> 7, d = idx & 127;
                float rv = sigf(gb0[r][d]);
                float zv = sigf(gb0[r][128 + d]);
                float nv = tanhfast(gb0[r][256 + d] + rv * gb0[r][384 + d]);
                float hold = st[r][256 + d];
                float hnew = (1.f - zv) * nv + zv * hold;
                st[r][256 + d] = hnew;
                st[r][d] = hnew;
            }
        }
        __syncthreads();
    }
}

// ---------------------------------------------------------------------------
// launch
// ---------------------------------------------------------------------------
extern "C" void kernel_launch(void* const* d_in, const int* in_sizes, int n_in,
                              void* d_out, int out_size)
{
    const float* x        = (const float*)d_in[0];
    const int*   pred_len = (const int*)  d_in[1];
    const float* wih0  = (const float*)d_in[2];
    const float* whh0  = (const float*)d_in[3];
    const float* bih0  = (const float*)d_in[4];
    const float* bhh0  = (const float*)d_in[5];
    const float* wih1  = (const float*)d_in[6];
    const float* whh1  = (const float*)d_in[7];
    const float* bih1  = (const float*)d_in[8];
    const float* bhh1  = (const float*)d_in[9];
    const float* gwih0 = (const float*)d_in[10];
    const float* gwhh0 = (const float*)d_in[11];
    const float* gbih0 = (const float*)d_in[12];
    const float* gbhh0 = (const float*)d_in[13];
    const float* gwih1 = (const float*)d_in[14];
    const float* gwhh1 = (const float*)d_in[15];
    const float* gbih1 = (const float*)d_in[16];
    const float* gbhh1 = (const float*)d_in[17];
    const float* brw   = (const float*)d_in[18];
    const float* brb   = (const float*)d_in[19];
    const float* fc1w  = (const float*)d_in[20];
    const float* fc1b  = (const float*)d_in[21];
    const float* fc2w  = (const float*)d_in[22];
    const float* fc2b  = (const float*)d_in[23];
    float* out = (float*)d_out;

    static bool attr_set = false;
    if (!attr_set) {
        cudaFuncSetAttribute(fused_kernel,
                             cudaFuncAttributeMaxDynamicSharedMemorySize, SMEM_BYTES);
        attr_set = true;
    }

    int prep_blocks = (SCRATCH_TOTAL + 255) / 256;
    prep_kernel<<<prep_blocks, 256>>>(wih0, whh0, bih0, bhh0,
                                      wih1, whh1, bih1, bhh1,
                                      gwih0, gwhh0, gbih0, gbhh0,
                                      gwih1, gwhh1, gbih1, gbhh1,
                                      brw, brb, fc1w, fc1b);
    fused_kernel<<<NBLOCKS, NTHREADS, SMEM_BYTES>>>(x, pred_len, fc2w, fc2b, out);
}